// round 14
// baseline (speedup 1.0000x reference)
#include <cuda_runtime.h>

// Problem constants: H=64, M=N=128, k=9, w=3
#define PTOT (64 * 128 * 128)
#define KNN  9

// ---- pass1 tile: 16 x 4 x 4; halo 18 x 6 x 6 ----
#define TX 16
#define TY 4
#define TZ 4
#define HX 18
#define HY 6
#define HROWS (HX * HY * 6)     // 648
#define HXY (HX * HY)           // 108

// ---- pass2 tile: 16 x 8 x 8, 1024 threads; value-row halo 18 x 10 x 10 ----
#define H3X 18
#define H3XY (18 * 10)          // 180
#define H3ROWS (18 * 10 * 10)   // 1800
// pass2 anat halo: 20 x 12 x 12
#define A3X 20
#define A3XY 240
#define A3ROWS (A3X * 12 * 12)  // 2880
#define SMEM2_FLOATS (H3ROWS * 9 + A3ROWS)          // 16200 + 2880
#define SMEM2_BYTES  (SMEM2_FLOATS * 4)             // 76320 B

// Scratch: ONLY codes — one uint4 per voxel, 9 code bytes in .x/.y/.z
// (byte = (oz<<4)|(oy<<2)|ox, offsets in 0..2), .w unused. 16.8 MB.
__device__ uint4 g_code4[PTOT];

// ---------------------------------------------------------------------------
// Pass 1: stable top-9 of 27 periodic window neighbors by |v - center|.
//   rank(c) = #{j<c: d_j <= d_c} + #{j>c: d_j < d_c}
// Branchless fixed-latency pair bodies: pre-add the c-side at compile time
// (init_c = c), then p = sign(bits(d_c) - bits(d_j)); rank_j += p*Wj;
// rank_c -= p*Wc. Integer compares on abs-bit patterns (order == float order
// for d >= 0). Center candidate 13 folded. Ranks byte-packed 4-per-u32.
// Epilogue: per-thread private scatter rows padded to 20 B (gcd(5,32)=1 ->
// the 27 predicated byte-STS are bank-conflict-free; was 4-way at 16 B).
// Each thread reads back only its OWN row -> no barrier, direct uint4 store.
// ---------------------------------------------------------------------------
__global__ __launch_bounds__(256) void pass1_kernel(const float* __restrict__ anat) {
    __shared__ float s_anat[HROWS];
    __shared__ unsigned char s_cb[256 * 20];

    int tid = threadIdx.x;
    int lx = tid & 15, ly = (tid >> 4) & 3, lz = tid >> 6;
    int x0 = blockIdx.x * TX, y0 = blockIdx.y * TY, z0 = blockIdx.z * TZ;

    for (int t = tid; t < HROWS; t += 256) {
        int hx = t % HX; int r = t / HX; int hy = r % HY; int hz = r / HY;
        int gx = (x0 + hx + 127) & 127;
        int gy = (y0 + hy + 127) & 127;
        int gz = (z0 + hz + 63) & 63;
        s_anat[t] = __ldg(&anat[(gz << 14) | (gy << 7) | gx]);
    }
    __syncthreads();

    int center = (lz + 1) * HXY + (ly + 1) * HX + (lx + 1);
    float ac = s_anat[center];

    int di[27];
#pragma unroll
    for (int oz = 0; oz < 3; ++oz)
#pragma unroll
        for (int oy = 0; oy < 3; ++oy)
#pragma unroll
            for (int ox = 0; ox < 3; ++ox) {
                int c = oz * 9 + oy * 3 + ox;
                float v = s_anat[center + (oz - 1) * HXY + (oy - 1) * HX + (ox - 1)];
                di[c] = (int)(__float_as_uint(v - ac) & 0x7fffffffu);
            }

    unsigned ri[7] = { 0x03020100u, 0x07060504u, 0x0B0A0908u, 0x0F0E0D0Cu,
                       0x13121110u, 0x17161514u, 0x001A1918u };

#pragma unroll
    for (int j = 0; j < 13; ++j) {
        unsigned p = ((unsigned)(-di[j])) >> 31;
        ri[j >> 2] += p * (1u << ((j & 3) * 8));
        ri[3]      -= p * (1u << 8);
    }

#pragma unroll
    for (int o = 1; o < 27; ++o)
#pragma unroll
        for (int j = 0; j + o < 27; ++j) {
            const int c = j + o;
            if (j == 13 || c == 13) continue;
            unsigned p = ((unsigned)(di[c] - di[j])) >> 31;   // d_j > d_c
            ri[j >> 2] += p * (1u << ((j & 3) * 8));
            ri[c >> 2] -= p * (1u << ((c & 3) * 8));
        }

    unsigned char* myrow = &s_cb[tid * 20];
#pragma unroll
    for (int c = 0; c < 27; ++c) {
        int r = (int)((ri[c >> 2] >> ((c & 3) * 8)) & 255u);
        if (r < KNN) {
            int oz = c / 9, rem = c - 9 * oz, oy = rem / 3, ox = rem - 3 * oy; // compile-time
            myrow[r] = (unsigned char)((oz << 4) | (oy << 2) | ox);
        }
    }
    // Own-row readback (no barrier needed), coalesced uint4 store.
    unsigned w0 = *(const unsigned*)&myrow[0];
    unsigned w1 = *(const unsigned*)&myrow[4];
    unsigned w2 = (unsigned)myrow[8];
    int i = ((z0 + lz) << 14) | ((y0 + ly) << 7) | (x0 + lx);
    g_code4[i] = make_uint4(w0, w1, w2, 0u);
}

// ---------------------------------------------------------------------------
// Pass 2: 1024 threads, 16x8x8 tile (rebuild redundancy 1.76 vs 2.11).
// Rebuild the 1800 value rows in dynamic smem (scalar stride 9; gcd(9,32)=1
// -> divergent reads near conflict-free) from a 20x12x12 anat halo + one
// LDG.128 of codes per row. 74.5 KB smem, 2 blocks/SM = 64 warps.
// Output staged through s9, written back as float4 (coalesced).
// ---------------------------------------------------------------------------
__global__ __launch_bounds__(1024) void pass2_kernel(const float* __restrict__ anat,
                                                     const float* __restrict__ ksig,
                                                     float* __restrict__ out) {
    extern __shared__ __align__(16) float smem_dyn[];
    float* s9  = smem_dyn;                 // H3ROWS * 9 floats, reused for out staging
    float* s_a = smem_dyn + H3ROWS * 9;    // A3ROWS floats

    int tid = threadIdx.x;
    int lx = tid & 15, ly = (tid >> 4) & 7, lz = tid >> 7;
    int x0 = blockIdx.x * 16, y0 = blockIdx.y * 8, z0 = blockIdx.z * 8;

    // anat halo 20x12x12 (offset -2).
    for (int t = tid; t < A3ROWS; t += 1024) {
        int ax = t % A3X; int r = t / A3X; int ay = r % 12; int az = r / 12;
        int gx = (x0 + ax + 126) & 127;
        int gy = (y0 + ay + 126) & 127;
        int gz = (z0 + az + 62) & 63;
        s_a[t] = __ldg(&anat[(gz << 14) | (gy << 7) | gx]);
    }

    int i = ((z0 + lz) << 14) | ((y0 + ly) << 7) | (x0 + lx);
    uint4 cwv = g_code4[i];
    unsigned cw[3] = { cwv.x, cwv.y, cwv.z };
    float ks = __ldg(&ksig[0]);
    __syncthreads();

    // Build the 1800 value rows: decode 9 codes per row, gather from s_a.
    for (int row = tid; row < H3ROWS; row += 1024) {
        int hx = row % H3X; int r = row / H3X; int hy = r % 10; int hz = r / 10;
        int gx = (x0 + hx + 127) & 127;
        int gy = (y0 + hy + 127) & 127;
        int gz = (z0 + hz + 63) & 63;
        uint4 w = g_code4[(gz << 14) | (gy << 7) | gx];
        unsigned ws[3] = { w.x, w.y, w.z };
        // row (hx,hy,hz) sits at anat-halo coords (hx+1,hy+1,hz+1); code
        // offsets are (oz-1,oy-1,ox-1) -> pre-subtract.
        int ac = (hz + 1) * A3XY + (hy + 1) * A3X + (hx + 1) - (A3XY + A3X + 1);
        float* d = &s9[row * 9];
#pragma unroll
        for (int t = 0; t < 9; ++t) {
            unsigned c = (ws[t >> 2] >> ((t & 3) * 8)) & 0xffu;
            int off = (int)(c >> 4) * A3XY + (int)((c >> 2) & 3) * A3X + (int)(c & 3);
            d[t] = s_a[ac + off];
        }
    }
    __syncthreads();

    int center = (lz + 1) * H3XY + (ly + 1) * H3X + (lx + 1) - (H3XY + H3X + 1);
    float wi[KNN];
#pragma unroll
    for (int t = 0; t < KNN; ++t) wi[t] = s9[(center + (H3XY + H3X + 1)) * 9 + t];

    // sigma = std(Wk, ddof=1), two-pass for fp32 stability
    float sum = 0.f;
#pragma unroll
    for (int t = 0; t < KNN; ++t) sum += wi[t];
    float mean = sum * (1.0f / 9.0f);
    float var = 0.f;
#pragma unroll
    for (int t = 0; t < KNN; ++t) { float d = wi[t] - mean; var += d * d; }
    var *= (1.0f / 8.0f);
    float sigma = sqrtf(var);
    bool  zeroSig = (sigma == 0.0f);
    float sig = zeroSig ? 1.0f : sigma;

    // logits = -(||diff|| / sigma / (sqrt(2)*ks))^2 = -s / (2*sigma^2*ks^2)
    float inv = 1.0f / (2.0f * sig * sig * ks * ks);

    float wie[KNN];
#pragma unroll
    for (int t = 0; t < KNN; ++t) wie[t] = wi[t] + 1e-6f;

    float logits[KNN];
#pragma unroll
    for (int j = 0; j < KNN; ++j) {
        int c = (int)((cw[j >> 2] >> ((j & 3) * 8)) & 0xffu);
        int rowc = center + (c >> 4) * H3XY + ((c >> 2) & 3) * H3X + (c & 3);
        const float* nr = &s9[rowc * 9];
        float s = 0.f;
#pragma unroll
        for (int t = 0; t < KNN; ++t) {
            float df = wie[t] - nr[t];
            s = fmaf(df, df, s);
        }
        logits[j] = zeroSig ? 0.0f : -(s * inv);
    }

    // softmax over the 9 neighbors
    float mx = logits[0];
#pragma unroll
    for (int j = 1; j < KNN; ++j) mx = fmaxf(mx, logits[j]);
    float e[KNN], se = 0.f;
#pragma unroll
    for (int j = 0; j < KNN; ++j) { e[j] = __expf(logits[j] - mx); se += e[j]; }
    float rse = 1.0f / se;

    __syncthreads();                       // all s9 reads done; reuse buffer
#pragma unroll
    for (int j = 0; j < KNN; ++j) s9[tid * KNN + j] = e[j] * rse;
    __syncthreads();

    // Coalesced out: 64 lines x 144 floats = 36 float4 per line, 2304 total.
    float4* s_out4 = (float4*)s9;
    for (int q = tid; q < 2304; q += 1024) {
        int line = q / 36, off = q - line * 36;
        int llz = line >> 3, lly = line & 7;
        int vox = ((z0 + llz) << 14) | ((y0 + lly) << 7) | x0;
        ((float4*)(out + (size_t)vox * KNN))[off] = s_out4[q];
    }
}

extern "C" void kernel_launch(void* const* d_in, const int* in_sizes, int n_in,
                              void* d_out, int out_size) {
    const float* anat = (const float*)d_in[0];
    const float* ksig = (const float*)d_in[1];
    float* out = (float*)d_out;

    dim3 grid1(128 / TX, 128 / TY, 64 / TZ);    // 4096 blocks
    pass1_kernel<<<grid1, 256>>>(anat);

    cudaFuncSetAttribute(pass2_kernel, cudaFuncAttributeMaxDynamicSharedMemorySize,
                         SMEM2_BYTES);
    dim3 grid2(128 / 16, 128 / 8, 64 / 8);      // 8 x 16 x 8 = 1024 blocks
    pass2_kernel<<<grid2, 1024, SMEM2_BYTES>>>(anat, ksig, out);
}